// round 12
// baseline (speedup 1.0000x reference)
#include <cuda_runtime.h>
#include <math.h>

#define Bb   8
#define Ss   4096
#define Dd   32
#define Nst  16
#define HIDn 128
#define Ll   64
#define CPB  64
#define NCHUNK 512
#define NGRP 8
#define GL   8
#define TOK  32768
#define XPAD 36                       // padded xp row stride (floats)
#define OUT_ELEMS ((size_t)TOK*Dd*Dd)

// ---------------- scratch ----------------------------------------------------
__device__ float g_P    [NCHUNK*Nst];
__device__ float g_sL   [NCHUNK*512];
__device__ float g_ylocA[TOK*Dd];     // y partial, n in [0,8)
__device__ float g_ylocB[TOK*Dd];     // y partial, n in [8,16)
__device__ float g_cpi  [TOK*Nst];
__device__ float g_hinL [NCHUNK*512];
__device__ float g_Hg   [Bb*NGRP*512];
__device__ float g_Plp  [Bb*NGRP*GL*Nst];
__device__ float g_SxP  [NCHUNK*Dd];
__device__ float g_SxxP [NCHUNK];
__device__ float g_lossB[Bb];

// ---------------- KP: 128-thread fused projection + split scan --------------
// grid = 512 (one chunk each), block = 128.
__global__ __launch_bounds__(128, 4) void kP(
    const float* __restrict__ x,   const float* __restrict__ A,
    const float* __restrict__ Win, const float* __restrict__ binp,
    const float* __restrict__ Wdt, const float* __restrict__ bdt,
    const float* __restrict__ Wdtr,
    const float* __restrict__ WB,  const float* __restrict__ WC)
{
    __shared__ __align__(16) float4 sa4 [Ll*4];      // a  [t][n]  4 KB
    __shared__ __align__(16) float4 sbd4[Ll*4];      // bd          4 KB
    __shared__ __align__(16) float4 sc4 [Ll*4];      // c           4 KB
    __shared__ __align__(16) float  sxp [Ll*XPAD];   // xp padded   9.2 KB
    __shared__ __align__(16) float4 sWin4[Dd*8];     // 4 KB
    __shared__ __align__(16) float4 sWB4[Dd*4], sWC4[Dd*4];
    __shared__ __align__(16) float4 sbin4[8];
    __shared__ float sweff[Dd], sA[Nst];
    __shared__ float szz[128];
    __shared__ float sSx2[2][Dd];
    __shared__ float sSxx2[2];
    __shared__ float sc0;

    int tid = threadIdx.x;
    int ch  = blockIdx.x;

    for (int i = tid; i < Dd*8; i += 128) sWin4[i] = ((const float4*)Win)[i];
    for (int i = tid; i < Dd*4; i += 128) { sWB4[i] = ((const float4*)WB)[i];
                                            sWC4[i] = ((const float4*)WC)[i]; }
    if (tid < 8) sbin4[tid] = ((const float4*)binp)[tid];
    if (tid < Dd) {
        float s = 0.f;
        #pragma unroll
        for (int r = 0; r < Nst; r++) s += Wdt[tid*Nst + r] * Wdtr[r];
        sweff[tid] = s;
    }
    if (tid == 32) {
        float s = 0.f;
        #pragma unroll
        for (int r = 0; r < Nst; r++) s += bdt[r] * Wdtr[r];
        sc0 = s;
    }
    if (tid >= 40 && tid < 40 + Nst) sA[tid-40] = A[tid-40];
    __syncthreads();

    int tl = tid & 63;            // token-in-chunk
    int hf = tid >> 6;            // output half (phase A) / B-vs-C (phase B)

    // ---- phase A: xp half per thread ----
    {
        float xr[32];
        const float4* xg = (const float4*)x + ((size_t)ch*Ll + tl)*8;
        #pragma unroll
        for (int j = 0; j < 8; j++) {
            float4 v = xg[j];
            xr[j*4+0] = v.x; xr[j*4+1] = v.y; xr[j*4+2] = v.z; xr[j*4+3] = v.w;
        }

        float xp16[16];
        #pragma unroll
        for (int j = 0; j < 4; j++) {
            float4 b = sbin4[hf*4 + j];
            xp16[j*4+0] = b.x; xp16[j*4+1] = b.y; xp16[j*4+2] = b.z; xp16[j*4+3] = b.w;
        }
        #pragma unroll
        for (int k = 0; k < 32; k++) {
            float xk = xr[k];
            #pragma unroll
            for (int j = 0; j < 4; j++) {
                float4 w = sWin4[k*8 + hf*4 + j];
                xp16[j*4+0] = fmaf(xk, w.x, xp16[j*4+0]);
                xp16[j*4+1] = fmaf(xk, w.y, xp16[j*4+1]);
                xp16[j*4+2] = fmaf(xk, w.z, xp16[j*4+2]);
                xp16[j*4+3] = fmaf(xk, w.w, xp16[j*4+3]);
            }
        }

        float zzp = 0.f;
        #pragma unroll
        for (int k = 0; k < 16; k++) zzp = fmaf(xp16[k], sweff[hf*16 + k], zzp);
        szz[hf*64 + tl] = zzp;

        float4* xprow = (float4*)&sxp[tl*XPAD + hf*16];
        #pragma unroll
        for (int j = 0; j < 4; j++)
            xprow[j] = make_float4(xp16[j*4+0], xp16[j*4+1], xp16[j*4+2], xp16[j*4+3]);
    }
    __syncthreads();

    // ---- phase B: B (sel=0) or C (sel=1) projection per token ----
    {
        int sel = hf;
        float xpr[32];
        const float4* xr4 = (const float4*)&sxp[tl*XPAD];
        #pragma unroll
        for (int j = 0; j < 8; j++) {
            float4 v = xr4[j];
            xpr[j*4+0] = v.x; xpr[j*4+1] = v.y; xpr[j*4+2] = v.z; xpr[j*4+3] = v.w;
        }

        float acc[16];
        #pragma unroll
        for (int n = 0; n < 16; n++) acc[n] = 0.f;
        const float4* W4 = sel ? sWC4 : sWB4;
        #pragma unroll
        for (int k = 0; k < 32; k++) {
            float xk = xpr[k];
            #pragma unroll
            for (int j = 0; j < 4; j++) {
                float4 w = W4[k*4 + j];
                acc[j*4+0] = fmaf(xk, w.x, acc[j*4+0]);
                acc[j*4+1] = fmaf(xk, w.y, acc[j*4+1]);
                acc[j*4+2] = fmaf(xk, w.z, acc[j*4+2]);
                acc[j*4+3] = fmaf(xk, w.w, acc[j*4+3]);
            }
        }

        if (sel == 0) {
            float zs = szz[tl] + szz[64 + tl] + sc0;
            float dtv = fmaxf(zs, 0.f) + log1pf(expf(-fabsf(zs)));
            #pragma unroll
            for (int j = 0; j < 4; j++) {
                sa4[tl*4 + j] = make_float4(expf(dtv*sA[j*4+0]), expf(dtv*sA[j*4+1]),
                                            expf(dtv*sA[j*4+2]), expf(dtv*sA[j*4+3]));
                sbd4[tl*4 + j] = make_float4(dtv*acc[j*4+0], dtv*acc[j*4+1],
                                             dtv*acc[j*4+2], dtv*acc[j*4+3]);
            }
        } else {
            #pragma unroll
            for (int j = 0; j < 4; j++)
                sc4[tl*4 + j] = make_float4(acc[j*4+0], acc[j*4+1], acc[j*4+2], acc[j*4+3]);
        }
    }
    __syncthreads();

    int warp = tid >> 5, lane = tid & 31;

    if (warp < 2) {
        // ---- scan: warp owns n in [8*warp, 8*warp+8), lane = d ----
        const float* sa = (const float*)sa4;          // [t*16+n]
        const float* sc = (const float*)sc4;
        int np = warp*8 + (lane & 7);

        float h[8];
        #pragma unroll
        for (int n = 0; n < 8; n++) h[n] = 0.f;
        float pis = 1.f;

        float* yw   = (warp ? g_ylocB : g_ylocA) + (size_t)ch*Ll*Dd;
        float* cpio = g_cpi + (size_t)ch*Ll*Nst;

        #pragma unroll 2
        for (int t = 0; t < Ll; t++) {
            float av[8], bv[8], cv[8];
            *(float4*)&av[0] = sa4 [t*4 + warp*2 + 0]; *(float4*)&av[4] = sa4 [t*4 + warp*2 + 1];
            *(float4*)&bv[0] = sbd4[t*4 + warp*2 + 0]; *(float4*)&bv[4] = sbd4[t*4 + warp*2 + 1];
            *(float4*)&cv[0] = sc4 [t*4 + warp*2 + 0]; *(float4*)&cv[4] = sc4 [t*4 + warp*2 + 1];
            float xv = sxp[t*XPAD + lane];

            float y0 = 0.f, y1 = 0.f;
            #pragma unroll
            for (int n = 0; n < 8; n += 2) {
                h[n+0] = fmaf(av[n+0], h[n+0], bv[n+0]*xv); y0 = fmaf(cv[n+0], h[n+0], y0);
                h[n+1] = fmaf(av[n+1], h[n+1], bv[n+1]*xv); y1 = fmaf(cv[n+1], h[n+1], y1);
            }
            yw[t*Dd + lane] = y0 + y1;

            pis *= sa[t*16 + np];
            if (lane < 8) cpio[t*Nst + np] = sc[t*16 + np] * pis;
        }

        float4* outL = (float4*)g_sL + (size_t)ch*128 + lane*4 + warp*2;
        outL[0] = make_float4(h[0],h[1],h[2],h[3]);
        outL[1] = make_float4(h[4],h[5],h[6],h[7]);
        if (lane < 8) g_P[ch*Nst + np] = pis;
    } else {
        // ---- x statistics, t-split across warps 2,3 ----
        int w2 = warp - 2;
        const float* xb = x + (size_t)ch*Ll*Dd + (size_t)w2*32*Dd;
        float s = 0.f, sq = 0.f;
        #pragma unroll 8
        for (int t = 0; t < 32; t++) {
            float v = xb[t*Dd + lane];
            s += v; sq = fmaf(v, v, sq);
        }
        sSx2[w2][lane] = s;
        #pragma unroll
        for (int m = 16; m >= 1; m >>= 1) sq += __shfl_xor_sync(0xffffffffu, sq, m);
        if (lane == 0) sSxx2[w2] = sq;
    }
    __syncthreads();

    if (tid < Dd)  g_SxP[ch*Dd + tid] = sSx2[0][tid] + sSx2[1][tid];
    if (tid == 32) g_SxxP[ch] = sSxx2[0] + sSxx2[1];
}

// ---------------- K3: per-batch combine + stat reduce + MLP loss ------------
__global__ __launch_bounds__(512) void k3(
    const float* __restrict__ Wd1, const float* __restrict__ bd1,
    const float* __restrict__ Wd2, const float* __restrict__ bd2,
    const float* __restrict__ Wd3, const float* __restrict__ bd3)
{
    __shared__ float sgend[NGRP*512];
    __shared__ float sPg[NGRP*Nst];
    __shared__ float sh[512];
    __shared__ float hrep[Nst], z1[HIDn], z2[HIDn], uu[Dd];
    __shared__ float sSxb[Dd], sSxxb;

    int b = blockIdx.x, off = threadIdx.x, n = off & 15;

    #pragma unroll
    for (int g = 0; g < NGRP; g++) {
        float lp[GL], ls[GL];
        #pragma unroll
        for (int j = 0; j < GL; j++) {
            int c = b*CPB + g*GL + j;
            lp[j] = g_P [c*Nst + n];
            ls[j] = g_sL[(size_t)c*512 + off];
        }
        float h = 0.f, pl = 1.f;
        #pragma unroll
        for (int j = 0; j < GL; j++) {
            int c = b*CPB + g*GL + j;
            g_hinL[(size_t)c*512 + off] = h;
            if (off < 16) g_Plp[((b*NGRP+g)*GL + j)*Nst + off] = pl;
            h  = fmaf(lp[j], h, ls[j]);
            pl *= lp[j];
        }
        sgend[g*512 + off] = h;
        if (off < 16) sPg[g*Nst + off] = pl;
    }
    __syncthreads();

    {
        float pg[NGRP], ge[NGRP];
        #pragma unroll
        for (int g = 0; g < NGRP; g++) {
            pg[g] = sPg[g*Nst + n];
            ge[g] = sgend[g*512 + off];
        }
        float h = 0.f;
        #pragma unroll
        for (int g = 0; g < NGRP; g++) {
            g_Hg[(size_t)(b*NGRP+g)*512 + off] = h;
            h = fmaf(pg[g], h, ge[g]);
        }
        sh[off] = h;
    }

    if (off < Dd) {
        float s = 0.f;
        #pragma unroll 8
        for (int k = 0; k < CPB; k++) s += g_SxP[(b*CPB + k)*Dd + off];
        sSxb[off] = s;
    } else if (off >= 32 && off < 64) {
        int l = off - 32;
        float s = g_SxxP[b*CPB + l] + g_SxxP[b*CPB + 32 + l];
        #pragma unroll
        for (int m = 16; m >= 1; m >>= 1) s += __shfl_xor_sync(0xffffffffu, s, m);
        if (l == 0) sSxxb = s;
    }
    __syncthreads();

    if (off < Nst) {
        float s = 0.f;
        #pragma unroll
        for (int d = 0; d < Dd; d++) s += sh[d*Nst + off];
        hrep[off] = s * (1.f/(float)Dd);
    }
    __syncthreads();
    if (off < HIDn) {
        float acc = bd1[off];
        #pragma unroll
        for (int nn = 0; nn < Nst; nn++) acc += hrep[nn] * Wd1[nn*HIDn + off];
        z1[off] = fmaxf(acc, 0.f);
    }
    __syncthreads();
    if (off < HIDn) {
        float acc = bd2[off];
        #pragma unroll 8
        for (int j = 0; j < HIDn; j++) acc += z1[j] * Wd2[j*HIDn + off];
        z2[off] = fmaxf(acc, 0.f);
    }
    __syncthreads();
    if (off < Dd) {
        float acc = bd3[off];
        #pragma unroll 8
        for (int j = 0; j < HIDn; j++) acc += z2[j] * Wd3[j*Dd + off];
        uu[off] = acc;
    }
    __syncthreads();
    if (off == 0) {
        float t1 = 0.f, t2 = 0.f;
        #pragma unroll
        for (int d = 0; d < Dd; d++) {
            t1 += uu[d]*uu[d];
            t2 += uu[d]*sSxb[d];
        }
        g_lossB[b] = (float)Ss * t1 - 2.f*t2 + sSxxb;
    }
}

// ---------------- K4: block-per-chunk y recombine + streaming expansion -----
__global__ __launch_bounds__(512) void k4(
    const float* __restrict__ Wout, const float* __restrict__ bout,
    float* __restrict__ out, long long out_size)
{
    __shared__ float shin[Dd*17];
    __shared__ float scpi[Ll*Nst];
    __shared__ float sy[Ll*Dd];
    __shared__ float4 sw[8], sb[8];

    int tid = threadIdx.x, ch = blockIdx.x;
    int bg = ch >> 3, j = ch & 7;

    {
        int d = tid >> 4, n = tid & 15;
        shin[d*17 + n] = fmaf(g_Plp[(bg*GL + j)*Nst + n],
                              g_Hg[(size_t)bg*512 + tid],
                              g_hinL[(size_t)ch*512 + tid]);
    }
    scpi[tid]       = g_cpi[(size_t)ch*1024 + tid];
    scpi[tid + 512] = g_cpi[(size_t)ch*1024 + 512 + tid];
    if (tid < 8)       sw[tid]   = ((const float4*)Wout)[tid];
    else if (tid < 16) sb[tid-8] = ((const float4*)bout)[tid-8];
    __syncthreads();

    #pragma unroll
    for (int k = 0; k < 4; k++) {
        int idx = tid + k*512;
        int t = idx >> 5, d = idx & 31;
        float y = g_ylocA[(size_t)ch*2048 + idx] + g_ylocB[(size_t)ch*2048 + idx];
        #pragma unroll
        for (int n = 0; n < Nst; n++)
            y = fmaf(scpi[t*Nst + n], shin[d*17 + n], y);
        sy[idx] = y;
    }
    __syncthreads();

    {
        int q = tid & 7, r0 = tid >> 3;
        float4 w4 = sw[q], b4 = sb[q];
        float4* o = (float4*)out + (size_t)ch*16384;
        #pragma unroll
        for (int k = 0; k < 32; k++) {
            int r = r0 + k*64;
            float y = sy[r];
            float4 v;
            v.x = fmaf(y, w4.x, b4.x);
            v.y = fmaf(y, w4.y, b4.y);
            v.z = fmaf(y, w4.z, b4.z);
            v.w = fmaf(y, w4.w, b4.w);
            __stcs(&o[r*8 + q], v);
        }
    }

    if (ch == 0 && tid == 0 && out_size > (long long)OUT_ELEMS) {
        float s = 0.f;
        #pragma unroll
        for (int b = 0; b < Bb; b++) s += g_lossB[b];
        out[out_size - 1] = s * (1.f/(float)(Bb*Ss));
    }
}

// ---------------- launch -----------------------------------------------------
extern "C" void kernel_launch(void* const* d_in, const int* in_sizes, int n_in,
                              void* d_out, int out_size)
{
    const float* x    = (const float*)d_in[0];
    const float* A    = (const float*)d_in[1];
    const float* Win  = (const float*)d_in[2];
    const float* binp = (const float*)d_in[3];
    const float* Wdt  = (const float*)d_in[4];
    const float* bdt  = (const float*)d_in[5];
    const float* Wdtr = (const float*)d_in[6];
    const float* WB   = (const float*)d_in[7];
    const float* WC   = (const float*)d_in[8];
    const float* Wout = (const float*)d_in[9];
    const float* bout = (const float*)d_in[10];
    const float* Wd1  = (const float*)d_in[11];
    const float* bd1  = (const float*)d_in[12];
    const float* Wd2  = (const float*)d_in[13];
    const float* bd2  = (const float*)d_in[14];
    const float* Wd3  = (const float*)d_in[15];
    const float* bd3  = (const float*)d_in[16];
    float* out = (float*)d_out;

    kP<<<NCHUNK, 128>>>(x, A, Win, binp, Wdt, bdt, Wdtr, WB, WC);
    k3<<<Bb, 512>>>(Wd1, bd1, Wd2, bd2, Wd3, bd3);
    k4<<<NCHUNK, 512>>>(Wout, bout, out, (long long)out_size);
}